// round 14
// baseline (speedup 1.0000x reference)
#include <cuda_runtime.h>

#define B_    16
#define LL_   256
#define LP_   1024
#define HID_  128
#define H_    8
#define HD_   1024

// ---------------- scratch ----------------
__device__ float g_l12[B_ * LL_ * 2 * HD_];             // [b][l][l1|l2]
__device__ float g_p1[B_ * LP_ * HD_];
__device__ float g_p2t[B_ * HD_ * LP_];                 // [b][h*128+d][p]
__device__ float g_att[(size_t)B_ * H_ * LL_ * LP_];    // unnormalized exp weights
__device__ float g_lig3[B_ * LL_ * HD_];
__device__ float g_prot3[B_ * LP_ * HD_];
__device__ float g_ligcat[B_ * LL_ * 2 * HID_];
__device__ float g_protcat[B_ * LP_ * 2 * HID_];
__device__ float g_ligr[B_ * LL_ * HID_];
__device__ float g_protr[B_ * LP_ * HID_];
__device__ float g_l2s[B_ * LL_ * HD_];                 // l2 scaled by row reciprocal sums
__device__ float g_epart[B_ * H_ * LL_ * 8];            // per-CTA-column partial row sums
__device__ float g_rs[B_ * H_ * LL_];                   // reciprocal row sums
__device__ float g_w[851968];
__device__ float g_b12[2048];

#define OW_L1  0
#define OW_L2  131072
#define OW_P1  262144
#define OW_P2  393216
#define OW_11  524288
#define OW_21  655360
#define OW_12  786432
#define OW_22  819200

// ---------------- helpers ----------------
__device__ __forceinline__ unsigned tf32_of(float f) {
    unsigned r;
    asm("cvt.rna.tf32.f32 %0, %1;" : "=r"(r) : "f"(f));
    return r;
}
__device__ __forceinline__ float tf32f(float f) { return __uint_as_float(tf32_of(f)); }

__device__ __forceinline__ void mma_tf32(float c[4], const unsigned a[4], const unsigned b[2]) {
    asm volatile(
        "mma.sync.aligned.m16n8k8.row.col.f32.tf32.tf32.f32 "
        "{%0,%1,%2,%3}, {%4,%5,%6,%7}, {%8,%9}, {%0,%1,%2,%3};"
        : "+f"(c[0]), "+f"(c[1]), "+f"(c[2]), "+f"(c[3])
        : "r"(a[0]), "r"(a[1]), "r"(a[2]), "r"(a[3]), "r"(b[0]), "r"(b[1]));
}

__device__ __forceinline__ void cp16(float* sm, const float* gm) {
    unsigned a = (unsigned)__cvta_generic_to_shared(sm);
    asm volatile("cp.async.cg.shared.global [%0], [%1], 16;" :: "r"(a), "l"(gm));
}
#define CP_COMMIT() asm volatile("cp.async.commit_group;" ::: "memory")
#define CP_WAIT2()  asm volatile("cp.async.wait_group 2;" ::: "memory")
#define CP_WAIT1()  asm volatile("cp.async.wait_group 1;" ::: "memory")

// shared epilogue. BIASM: 0 none, 1 bias[col], 2 bias[row], 3 row-scale by bias[row]
template<int BIASM, bool RELU, bool ROUND>
__device__ __forceinline__ void epilogue(float acc[4][4][4], float* C, const float* bias,
                                         int bm, int bn, int ldc, int mw, int nw, int g, int tg)
{
#pragma unroll
    for (int mt = 0; mt < 4; mt++) {
#pragma unroll
        for (int nt = 0; nt < 4; nt++) {
            int row = bm + mw * 64 + mt * 16 + g;
            int col = bn + nw * 32 + nt * 8 + 2 * tg;
            float x0 = acc[mt][nt][0], x1 = acc[mt][nt][1];
            float x2 = acc[mt][nt][2], x3 = acc[mt][nt][3];
            if (BIASM == 1) {
                float b0 = bias[col], b1 = bias[col + 1];
                x0 += b0; x1 += b1; x2 += b0; x3 += b1;
            } else if (BIASM == 2) {
                float br = bias[row], br8 = bias[row + 8];
                x0 += br; x1 += br; x2 += br8; x3 += br8;
            } else if (BIASM == 3) {
                float br = bias[row], br8 = bias[row + 8];
                x0 *= br; x1 *= br; x2 *= br8; x3 *= br8;
            }
            if (RELU) {
                x0 = fmaxf(x0, 0.f); x1 = fmaxf(x1, 0.f);
                x2 = fmaxf(x2, 0.f); x3 = fmaxf(x3, 0.f);
            }
            if (ROUND) { x0 = tf32f(x0); x1 = tf32f(x1); x2 = tf32f(x2); x3 = tf32f(x3); }
            *(float2*)(C + (size_t)row * ldc + col) = make_float2(x0, x1);
            *(float2*)(C + (size_t)(row + 8) * ldc + col) = make_float2(x2, x3);
        }
    }
}

// ================= cp-body: A [m][k], B [n][k], 3-stage cp.async =================
template<int BIASM, bool RELU, bool ROUND>
__device__ __forceinline__ void cp_body(const float* __restrict__ A, const float* __restrict__ B,
                                        const float* __restrict__ bias, float* __restrict__ C,
                                        int K, int lda, int ldb, int ldc,
                                        int bm, int bn, float* sm)
{
    const int tid  = threadIdx.x;
    const int lane = tid & 31, warp = tid >> 5;
    const int mw = warp & 1, nw = warp >> 1;
    const int g = lane >> 2, tg = lane & 3;

    const int r0 = tid >> 2,  kc = (tid & 3) << 2;
    const int r1 = r0 + 64;
    const float* gA0 = A + (size_t)(bm + r0) * lda + kc;
    const float* gA1 = A + (size_t)(bm + r1) * lda + kc;
    const float* gB0 = B + (size_t)(bn + r0) * ldb + kc;
    const float* gB1 = B + (size_t)(bn + r1) * ldb + kc;
    const int so = r0 * 16 + kc;
    const int s1 = r1 * 16 + kc;

    float acc[4][4][4];
#pragma unroll
    for (int i = 0; i < 4; i++)
#pragma unroll
        for (int j = 0; j < 4; j++)
#pragma unroll
            for (int r = 0; r < 4; r++) acc[i][j][r] = 0.f;

    const int nk = K >> 4;

    auto issue = [&](int t) {
        float* base = sm + (t % 3) * 4096;
        const size_t ko = (size_t)t << 4;
        cp16(base + so,        gA0 + ko);
        cp16(base + s1,        gA1 + ko);
        cp16(base + 2048 + so, gB0 + ko);
        cp16(base + 2048 + s1, gB1 + ko);
    };

    issue(0); CP_COMMIT();
    if (nk > 1) issue(1);
    CP_COMMIT();

    for (int t = 0; t < nk; t++) {
        if (t + 2 < nk) issue(t + 2);
        CP_COMMIT();
        CP_WAIT2();
        __syncthreads();

        const float* As = sm + (t % 3) * 4096;
        const float* Bs = As + 2048;

        float4 bf[4];
#pragma unroll
        for (int nt = 0; nt < 4; nt++)
            bf[nt] = *(const float4*)(Bs + (nw * 32 + nt * 8 + g) * 16 + 4 * tg);

#pragma unroll
        for (int mt = 0; mt < 4; mt++) {
            const int m0 = mw * 64 + mt * 16;
            float4 a0 = *(const float4*)(As + (m0 + g) * 16 + 4 * tg);
            float4 a1 = *(const float4*)(As + (m0 + g + 8) * 16 + 4 * tg);
            unsigned af0[4] = {__float_as_uint(a0.x), __float_as_uint(a1.x),
                               __float_as_uint(a0.y), __float_as_uint(a1.y)};
            unsigned af1[4] = {__float_as_uint(a0.z), __float_as_uint(a1.z),
                               __float_as_uint(a0.w), __float_as_uint(a1.w)};
#pragma unroll
            for (int nt = 0; nt < 4; nt++) {
                unsigned b0[2] = {__float_as_uint(bf[nt].x), __float_as_uint(bf[nt].y)};
                mma_tf32(acc[mt][nt], af0, b0);
            }
#pragma unroll
            for (int nt = 0; nt < 4; nt++) {
                unsigned b1[2] = {__float_as_uint(bf[nt].z), __float_as_uint(bf[nt].w)};
                mma_tf32(acc[mt][nt], af1, b1);
            }
        }
        __syncthreads();
    }

    epilogue<BIASM, RELU, ROUND>(acc, C, bias, bm, bn, ldc, mw, nw, g, tg);
}

// ================= kk-body: A [k][m], B [k][n], 2-stage cp.async =================
template<bool ROUND>
__device__ __forceinline__ void kk_body(const float* __restrict__ A, const float* __restrict__ B,
                                        float* __restrict__ C,
                                        int K, int lda, int ldb, int ldc,
                                        int bm, int bn, float* sm)
{
    const int tid  = threadIdx.x;
    const int lane = tid & 31, warp = tid >> 5;
    const int mw = warp & 1, nw = warp >> 1;
    const int g = lane >> 2, tg = lane & 3;

    const int STAGE = 2 * 16 * 136;

    const int kr0 = tid >> 5;
    const int kr1 = kr0 + 8;
    const int cc  = (tid & 31) << 2;
    const float* gA0 = A + (size_t)kr0 * lda + bm + cc;
    const float* gA1 = A + (size_t)kr1 * lda + bm + cc;
    const float* gB0 = B + (size_t)kr0 * ldb + bn + cc;
    const float* gB1 = B + (size_t)kr1 * ldb + bn + cc;
    const int soA0 = kr0 * 136 + cc, soA1 = kr1 * 136 + cc;

    float acc[4][4][4];
#pragma unroll
    for (int i = 0; i < 4; i++)
#pragma unroll
        for (int j = 0; j < 4; j++)
#pragma unroll
            for (int r = 0; r < 4; r++) acc[i][j][r] = 0.f;

    const int nk = K >> 4;

    auto issue = [&](int t) {
        float* base = sm + (t & 1) * STAGE;
        const size_t ko = (size_t)t * 16;
        cp16(base + soA0,              gA0 + ko * lda);
        cp16(base + soA1,              gA1 + ko * lda);
        cp16(base + 16 * 136 + soA0,   gB0 + ko * ldb);
        cp16(base + 16 * 136 + soA1,   gB1 + ko * ldb);
    };

    issue(0); CP_COMMIT();

    for (int t = 0; t < nk; t++) {
        if (t + 1 < nk) issue(t + 1);
        CP_COMMIT();
        CP_WAIT1();
        __syncthreads();

        const float* As = sm + (t & 1) * STAGE;
        const float* Bs = As + 16 * 136;

#pragma unroll
        for (int ks = 0; ks < 16; ks += 8) {
            unsigned bf[4][2];
#pragma unroll
            for (int nt = 0; nt < 4; nt++) {
                int n = nw * 32 + nt * 8 + g;
                bf[nt][0] = __float_as_uint(Bs[(ks + tg) * 136 + n]);
                bf[nt][1] = __float_as_uint(Bs[(ks + tg + 4) * 136 + n]);
            }
#pragma unroll
            for (int mt = 0; mt < 4; mt++) {
                int m0 = mw * 64 + mt * 16;
                unsigned af[4];
                af[0] = __float_as_uint(As[(ks + tg) * 136 + m0 + g]);
                af[1] = __float_as_uint(As[(ks + tg) * 136 + m0 + g + 8]);
                af[2] = __float_as_uint(As[(ks + tg + 4) * 136 + m0 + g]);
                af[3] = __float_as_uint(As[(ks + tg + 4) * 136 + m0 + g + 8]);
#pragma unroll
                for (int nt = 0; nt < 4; nt++)
                    mma_tf32(acc[mt][nt], af, bf[nt]);
            }
        }
        __syncthreads();
    }

    epilogue<0, false, ROUND>(acc, C, nullptr, bm, bn, ldc, mw, nw, g, tg);
}

// ================= energy kernel: e = l1 @ p1^T, epilogue writes exp weights =================
__global__ __launch_bounds__(256, 2)
void gemm_energy(const float* __restrict__ l12g, const float* __restrict__ p1g,
                 const float* __restrict__ inter,
                 float* __restrict__ att, float* __restrict__ epart)
{
    extern __shared__ float sm[];
    const int nx = blockIdx.x, my = blockIdx.y, z = blockIdx.z;
    const int zb = z >> 3, zh = z & 7;
    const float* A  = l12g + (size_t)zb * (LL_ * 2 * HD_) + zh * 128;   // lda 2048
    const float* B  = p1g  + (size_t)zb * (LP_ * HD_) + zh * 128;       // ldb 1024
    float* C = att + (size_t)zb * ((size_t)H_ * LL_ * LP_) + (size_t)zh * (LL_ * LP_);
    const float* ipt = inter + (size_t)zb * (LL_ * LP_);

    const int lda = 2048, ldb = 1024, ldc = 1024;
    const int bm = my * 128, bn = nx * 128;

    const int tid  = threadIdx.x;
    const int lane = tid & 31, warp = tid >> 5;
    const int mw = warp & 1, nw = warp >> 1;
    const int g = lane >> 2, tg = lane & 3;

    const int r0 = tid >> 2,  kc = (tid & 3) << 2;
    const int r1 = r0 + 64;
    const float* gA0 = A + (size_t)(bm + r0) * lda + kc;
    const float* gA1 = A + (size_t)(bm + r1) * lda + kc;
    const float* gB0 = B + (size_t)(bn + r0) * ldb + kc;
    const float* gB1 = B + (size_t)(bn + r1) * ldb + kc;
    const int so = r0 * 16 + kc;
    const int s1 = r1 * 16 + kc;

    float acc[4][4][4];
#pragma unroll
    for (int i = 0; i < 4; i++)
#pragma unroll
        for (int j = 0; j < 4; j++)
#pragma unroll
            for (int r = 0; r < 4; r++) acc[i][j][r] = 0.f;

    const int nk = 8;   // K=128

    auto issue = [&](int t) {
        float* base = sm + (t % 3) * 4096;
        const size_t ko = (size_t)t << 4;
        cp16(base + so,        gA0 + ko);
        cp16(base + s1,        gA1 + ko);
        cp16(base + 2048 + so, gB0 + ko);
        cp16(base + 2048 + s1, gB1 + ko);
    };

    issue(0); CP_COMMIT();
    issue(1); CP_COMMIT();

    for (int t = 0; t < nk; t++) {
        if (t + 2 < nk) issue(t + 2);
        CP_COMMIT();
        CP_WAIT2();
        __syncthreads();

        const float* As = sm + (t % 3) * 4096;
        const float* Bs = As + 2048;

        float4 bf[4];
#pragma unroll
        for (int nt = 0; nt < 4; nt++)
            bf[nt] = *(const float4*)(Bs + (nw * 32 + nt * 8 + g) * 16 + 4 * tg);

#pragma unroll
        for (int mt = 0; mt < 4; mt++) {
            const int m0 = mw * 64 + mt * 16;
            float4 a0 = *(const float4*)(As + (m0 + g) * 16 + 4 * tg);
            float4 a1 = *(const float4*)(As + (m0 + g + 8) * 16 + 4 * tg);
            unsigned af0[4] = {__float_as_uint(a0.x), __float_as_uint(a1.x),
                               __float_as_uint(a0.y), __float_as_uint(a1.y)};
            unsigned af1[4] = {__float_as_uint(a0.z), __float_as_uint(a1.z),
                               __float_as_uint(a0.w), __float_as_uint(a1.w)};
#pragma unroll
            for (int nt = 0; nt < 4; nt++) {
                unsigned b0[2] = {__float_as_uint(bf[nt].x), __float_as_uint(bf[nt].y)};
                mma_tf32(acc[mt][nt], af0, b0);
            }
#pragma unroll
            for (int nt = 0; nt < 4; nt++) {
                unsigned b1[2] = {__float_as_uint(bf[nt].z), __float_as_uint(bf[nt].w)};
                mma_tf32(acc[mt][nt], af1, b1);
            }
        }
        __syncthreads();
    }

    // ---- epilogue: exp weights + partial row sums (float2 inter loads) ----
    const float inv = 0.08838834764831845f;
    float rsum[4][2];
#pragma unroll
    for (int mt = 0; mt < 4; mt++) { rsum[mt][0] = 0.f; rsum[mt][1] = 0.f; }

#pragma unroll
    for (int mt = 0; mt < 4; mt++) {
#pragma unroll
        for (int nt = 0; nt < 4; nt++) {
            int row = bm + mw * 64 + mt * 16 + g;
            int col = bn + nw * 32 + nt * 8 + 2 * tg;
            float2 ia = *(const float2*)(ipt + (size_t)row * LP_ + col);
            float2 ib = *(const float2*)(ipt + (size_t)(row + 8) * LP_ + col);
            float w0 = tf32f(__expf(acc[mt][nt][0] * inv * ia.x));
            float w1 = tf32f(__expf(acc[mt][nt][1] * inv * ia.y));
            float w2 = tf32f(__expf(acc[mt][nt][2] * inv * ib.x));
            float w3 = tf32f(__expf(acc[mt][nt][3] * inv * ib.y));
            *(float2*)(C + (size_t)row * ldc + col) = make_float2(w0, w1);
            *(float2*)(C + (size_t)(row + 8) * ldc + col) = make_float2(w2, w3);
            rsum[mt][0] += w0 + w1;
            rsum[mt][1] += w2 + w3;
        }
    }

#pragma unroll
    for (int mt = 0; mt < 4; mt++) {
#pragma unroll
        for (int r = 0; r < 2; r++) {
            float v = rsum[mt][r];
            v += __shfl_xor_sync(0xffffffffu, v, 1);
            v += __shfl_xor_sync(0xffffffffu, v, 2);
            if (tg == 0)
                sm[nw * 128 + mw * 64 + mt * 16 + g + r * 8] = v;
        }
    }
    __syncthreads();
    if (tid < 128) {
        float s = sm[tid] + sm[128 + tid] + sm[256 + tid] + sm[384 + tid];
        epart[((size_t)z * 256 + bm + tid) * 8 + nx] = s;
    }
}

// reciprocal row sums
__global__ void reduce_rs(const float* __restrict__ epart, float* __restrict__ rs)
{
    int i = blockIdx.x * 256 + threadIdx.x;
    const float* p = epart + (size_t)i * 8;
    float s = p[0] + p[1] + p[2] + p[3] + p[4] + p[5] + p[6] + p[7];
    rs[i] = 1.0f / s;
}

// l2s[b][l][h*128+d] = tf32( l2 * rs[b,h,l] )
__global__ void scale_l2(const float4* __restrict__ l12v, const float* __restrict__ rs,
                         float4* __restrict__ l2s)
{
    int i = blockIdx.x * 256 + threadIdx.x;     // 1048576 -> 4096 blocks
    int hd4 = i & 255, l = (i >> 8) & 255, b = i >> 16;
    int h = hd4 >> 5;
    float r = rs[((size_t)b * 8 + h) * 256 + l];
    float4 v = l12v[(size_t)b * (LL_ * 2 * HD_ / 4) + (size_t)l * (2 * HD_ / 4) + HD_ / 4 + hd4];
    l2s[(size_t)b * (LL_ * HD_ / 4) + (size_t)l * (HD_ / 4) + hd4] =
        make_float4(tf32f(v.x * r), tf32f(v.y * r), tf32f(v.z * r), tf32f(v.w * r));
}

// ================= global kernels =================
__global__ __launch_bounds__(256, 2)
void gemm_proj(const float* __restrict__ ligr, const float* __restrict__ protr,
               const float* __restrict__ w, const float* __restrict__ bb,
               const float* __restrict__ bp1, const float* __restrict__ bp2,
               float* __restrict__ l12, float* __restrict__ p1, float* __restrict__ p2t)
{
    extern __shared__ float sm[];
    int id = blockIdx.x;
    if (id < 512) {
        int my = id >> 4, nx = id & 15;
        cp_body<1, true, true>(ligr, w + OW_L1, bb, l12,
                               128, 128, 128, 2048, my * 128, nx * 128, sm);
    } else if (id < 1536) {
        int id2 = id - 512;
        int my = id2 >> 3, nx = id2 & 7;
        cp_body<1, true, true>(protr, w + OW_P1, bp1, p1,
                               128, 128, 128, 1024, my * 128, nx * 128, sm);
    } else {
        int id2 = id - 1536;
        int zb = id2 >> 6, rem = id2 & 63;
        int my = rem >> 3, nx = rem & 7;
        cp_body<2, true, true>(w + OW_P2, protr + (size_t)zb * LP_ * HID_, bp2,
                               p2t + (size_t)zb * HD_ * LP_,
                               128, 128, 128, 1024, my * 128, nx * 128, sm);
    }
}

template<int BIASM, bool RELU, bool ROUND>
__global__ __launch_bounds__(256, 2)
void gemm_cp2(const float* __restrict__ A0, const float* __restrict__ B0,
              const float* __restrict__ b0, float* __restrict__ C0, int n0,
              const float* __restrict__ A1, const float* __restrict__ B1,
              const float* __restrict__ b1, float* __restrict__ C1,
              int K, int lda, int ldb, int ldc)
{
    extern __shared__ float sm[];
    int id = blockIdx.x;
    if (id < n0)
        cp_body<BIASM, RELU, ROUND>(A0, B0, b0, C0, K, lda, ldb, ldc, id * 128, 0, sm);
    else
        cp_body<BIASM, RELU, ROUND>(A1, B1, b1, C1, K, lda, ldb, ldc, (id - n0) * 128, 0, sm);
}

// fused attention-output, z-interleaved: 10 CTAs per (b,h) group launch adjacently
// so concurrent CTAs share the 1MB att slice in L2.
// id = z*10 + r : r<2 -> lig3 (my=r, cp-body, K=1024); r>=2 -> prot3 (my=r-2, kk-body, K=256)
__global__ __launch_bounds__(256, 2)
void gemm_av(const float* __restrict__ att, const float* __restrict__ p2t,
             const float* __restrict__ l2s, const float* __restrict__ rs,
             float* __restrict__ lig3, float* __restrict__ prot3)
{
    extern __shared__ float sm[];
    int id = blockIdx.x;
    int z = id / 10, r = id % 10;
    int zb = z >> 3, zh = z & 7;
    const float* A = att + (size_t)zb * ((size_t)H_ * LL_ * LP_) + (size_t)zh * (LL_ * LP_);
    if (r < 2) {
        const float* Bp = p2t + (size_t)zb * (HD_ * LP_) + (size_t)zh * (128 * LP_);
        float* C = lig3 + (size_t)zb * (LL_ * HD_) + zh * 128;
        const float* rsz = rs + (size_t)z * 256;
        cp_body<3, false, true>(A, Bp, rsz, C, 1024, LP_, LP_, HD_, r * 128, 0, sm);
    } else {
        const float* Bl = l2s + (size_t)zb * (LL_ * HD_) + zh * 128;
        float* C = prot3 + (size_t)zb * (LP_ * HD_) + zh * 128;
        kk_body<true>(A, Bl, C, 256, LP_, HD_, HD_, (r - 2) * 128, 0, sm);
    }
}

// ---------------- merged preprocessing ----------------
// 131072 + 524288 + 2048 = 657408 threads -> 2568 blocks of 256
__global__ void preproc(const float4* __restrict__ lig, const float4* __restrict__ prot,
                        const float* __restrict__ bl1, const float* __restrict__ bl2,
                        float4* __restrict__ ligr, float4* __restrict__ protr,
                        float4* __restrict__ lcat, float4* __restrict__ pcat,
                        float* __restrict__ bb)
{
    int i = blockIdx.x * 256 + threadIdx.x;
    const int n1 = B_ * LL_ * HID_ / 4;   // 131072
    const int n2 = B_ * LP_ * HID_ / 4;   // 524288
    if (i < n1) {
        float4 v = lig[i];
        v = make_float4(tf32f(v.x), tf32f(v.y), tf32f(v.z), tf32f(v.w));
        ligr[i] = v;
        int r = i >> 5, c = i & 31;
        lcat[(size_t)r * 64 + 32 + c] = v;
    } else if (i < n1 + n2) {
        int j = i - n1;
        float4 v = prot[j];
        v = make_float4(tf32f(v.x), tf32f(v.y), tf32f(v.z), tf32f(v.w));
        protr[j] = v;
        int r = j >> 5, c = j & 31;
        pcat[(size_t)r * 64 + 32 + c] = v;
    } else {
        int j = i - n1 - n2;
        if (j < 1024) bb[j] = bl1[j];
        else if (j < 2048) bb[j] = bl2[j - 1024];
    }
}

__global__ void transpose_round8(const float* w0, const float* w1, const float* w2,
                                 const float* w3, const float* w4, const float* w5,
                                 const float* w6, const float* w7, float* wb)
{
    const float* ins[8] = {w0, w1, w2, w3, w4, w5, w6, w7};
    const int Rs[8]   = {128, 128, 128, 128, 1024, 1024, 256, 256};
    const int Cs[8]   = {1024, 1024, 1024, 1024, 128, 128, 128, 128};
    const int offs[8] = {OW_L1, OW_L2, OW_P1, OW_P2, OW_11, OW_21, OW_12, OW_22};
    int zi = blockIdx.z;
    int R = Rs[zi], C = Cs[zi];
    int bx = blockIdx.x * 32, by = blockIdx.y * 32;
    if (bx >= C || by >= R) return;
    const float* in = ins[zi];
    float* out = wb + offs[zi];

    __shared__ float t[32][33];
    int tx = threadIdx.x, ty = threadIdx.y;
#pragma unroll
    for (int j = 0; j < 32; j += 8)
        t[ty + j][tx] = in[(size_t)(by + ty + j) * C + bx + tx];
    __syncthreads();
#pragma unroll
    for (int j = 0; j < 32; j += 8)
        out[(size_t)(bx + ty + j) * R + by + tx] = tf32f(t[tx][ty + j]);
}

// ---------------- launcher ----------------
extern "C" void kernel_launch(void* const* d_in, const int* in_sizes, int n_in,
                              void* d_out, int out_size)
{
    const float* ligand = (const float*)d_in[0];
    const float* prot   = (const float*)d_in[1];
    const float* inter  = (const float*)d_in[2];
    const float* Wl1 = (const float*)d_in[3];  const float* bl1 = (const float*)d_in[4];
    const float* Wl2 = (const float*)d_in[5];  const float* bl2 = (const float*)d_in[6];
    const float* Wp1 = (const float*)d_in[7];  const float* bp1 = (const float*)d_in[8];
    const float* Wp2 = (const float*)d_in[9];  const float* bp2 = (const float*)d_in[10];
    const float* W11 = (const float*)d_in[11]; const float* b11 = (const float*)d_in[12];
    const float* W12 = (const float*)d_in[13]; const float* b12 = (const float*)d_in[14];
    const float* W21 = (const float*)d_in[15]; const float* b21 = (const float*)d_in[16];
    const float* W22 = (const float*)d_in[17]; const float* b22 = (const float*)d_in[18];

    float* out_lig  = (float*)d_out;
    float* out_prot = out_lig + (size_t)B_ * LL_ * HID_;

    float *l12, *p1, *p2t, *att, *lig3, *prot3, *lcat, *pcat, *ligr, *protr, *w, *bb;
    float *l2s, *epart, *rs;
    cudaGetSymbolAddress((void**)&l12, g_l12);
    cudaGetSymbolAddress((void**)&p1, g_p1);
    cudaGetSymbolAddress((void**)&p2t, g_p2t);
    cudaGetSymbolAddress((void**)&att, g_att);
    cudaGetSymbolAddress((void**)&lig3, g_lig3);
    cudaGetSymbolAddress((void**)&prot3, g_prot3);
    cudaGetSymbolAddress((void**)&lcat, g_ligcat);
    cudaGetSymbolAddress((void**)&pcat, g_protcat);
    cudaGetSymbolAddress((void**)&ligr, g_ligr);
    cudaGetSymbolAddress((void**)&protr, g_protr);
    cudaGetSymbolAddress((void**)&w, g_w);
    cudaGetSymbolAddress((void**)&bb, g_b12);
    cudaGetSymbolAddress((void**)&l2s, g_l2s);
    cudaGetSymbolAddress((void**)&epart, g_epart);
    cudaGetSymbolAddress((void**)&rs, g_rs);

    dim3 blk(256);
    const int SMEM = 49152;

    // --- preprocessing ---
    preproc<<<2568, 256>>>((const float4*)ligand, (const float4*)prot, bl1, bl2,
                           (float4*)ligr, (float4*)protr,
                           (float4*)lcat, (float4*)pcat, bb);
    transpose_round8<<<dim3(32, 32, 8), dim3(32, 8)>>>(
        Wl1, Wl2, Wp1, Wp2, W11, W21, W12, W22, w);

    // --- all three projections in one 2560-CTA launch ---
    gemm_proj<<<2560, blk, SMEM>>>(ligr, protr, w, bb, bp1, bp2, l12, p1, p2t);

    // --- energy with fused exp/gating epilogue + partial row sums ---
    gemm_energy<<<dim3(8, 2, 128), blk, SMEM>>>(l12, p1, inter, att, epart);

    // --- reciprocal row sums + scaled l2 ---
    reduce_rs<<<128, 256>>>(epart, rs);
    scale_l2<<<4096, 256>>>((const float4*)l12, rs, (float4*)l2s);

    // --- fused lig3 + prot3 (1280 CTAs, z-interleaved for att L2 reuse) ---
    gemm_av<<<1280, blk, SMEM>>>(att, p2t, l2s, rs, lig3, prot3);

    // --- paired branch MLP stage 1 ---
    gemm_cp2<1,false,true><<<160, blk, SMEM>>>(
        lig3,  w + OW_11, b11, lcat, 32,
        prot3, w + OW_21, b21, pcat,
        1024, 1024, 1024, 256);

    // --- paired branch MLP stage 2 ---
    gemm_cp2<1,true,false><<<160, blk, SMEM>>>(
        lcat, w + OW_12, b12, out_lig, 32,
        pcat, w + OW_22, b22, out_prot,
        256, 256, 256, 128);
}

// round 15
// speedup vs baseline: 1.0760x; 1.0760x over previous
#include <cuda_runtime.h>

#define B_    16
#define LL_   256
#define LP_   1024
#define HID_  128
#define H_    8
#define HD_   1024

// ---------------- scratch ----------------
__device__ float g_l12[B_ * LL_ * 2 * HD_];             // [b][l][l1|l2]
__device__ float g_p1[B_ * LP_ * HD_];
__device__ float g_p2t[B_ * HD_ * LP_];                 // [b][h*128+d][p]
__device__ float g_att[(size_t)B_ * H_ * LL_ * LP_];    // unnormalized exp weights
__device__ float g_lig3[B_ * LL_ * HD_];
__device__ float g_prot3[B_ * LP_ * HD_];
__device__ float g_ligcat[B_ * LL_ * 2 * HID_];
__device__ float g_protcat[B_ * LP_ * 2 * HID_];
__device__ float g_ligr[B_ * LL_ * HID_];
__device__ float g_protr[B_ * LP_ * HID_];
__device__ float g_l2s[B_ * LL_ * HD_];                 // l2 scaled by row reciprocal sums
__device__ float g_epart[B_ * H_ * LL_ * 8];            // per-CTA-column partial row sums
__device__ float g_rs[B_ * H_ * LL_];                   // reciprocal row sums
__device__ float g_w[851968];
__device__ float g_b12[2048];

#define OW_L1  0
#define OW_L2  131072
#define OW_P1  262144
#define OW_P2  393216
#define OW_11  524288
#define OW_21  655360
#define OW_12  786432
#define OW_22  819200

// ---------------- helpers ----------------
__device__ __forceinline__ unsigned tf32_of(float f) {
    unsigned r;
    asm("cvt.rna.tf32.f32 %0, %1;" : "=r"(r) : "f"(f));
    return r;
}
__device__ __forceinline__ float tf32f(float f) { return __uint_as_float(tf32_of(f)); }

__device__ __forceinline__ void mma_tf32(float c[4], const unsigned a[4], const unsigned b[2]) {
    asm volatile(
        "mma.sync.aligned.m16n8k8.row.col.f32.tf32.tf32.f32 "
        "{%0,%1,%2,%3}, {%4,%5,%6,%7}, {%8,%9}, {%0,%1,%2,%3};"
        : "+f"(c[0]), "+f"(c[1]), "+f"(c[2]), "+f"(c[3])
        : "r"(a[0]), "r"(a[1]), "r"(a[2]), "r"(a[3]), "r"(b[0]), "r"(b[1]));
}

__device__ __forceinline__ void cp16(float* sm, const float* gm) {
    unsigned a = (unsigned)__cvta_generic_to_shared(sm);
    asm volatile("cp.async.cg.shared.global [%0], [%1], 16;" :: "r"(a), "l"(gm));
}
#define CP_COMMIT() asm volatile("cp.async.commit_group;" ::: "memory")
#define CP_WAIT2()  asm volatile("cp.async.wait_group 2;" ::: "memory")
#define CP_WAIT1()  asm volatile("cp.async.wait_group 1;" ::: "memory")

// shared epilogue. BIASM: 0 none, 1 bias[col], 2 bias[row], 3 row-scale by bias[row]
template<int BIASM, bool RELU, bool ROUND>
__device__ __forceinline__ void epilogue(float acc[4][4][4], float* C, const float* bias,
                                         int bm, int bn, int ldc, int mw, int nw, int g, int tg)
{
#pragma unroll
    for (int mt = 0; mt < 4; mt++) {
#pragma unroll
        for (int nt = 0; nt < 4; nt++) {
            int row = bm + mw * 64 + mt * 16 + g;
            int col = bn + nw * 32 + nt * 8 + 2 * tg;
            float x0 = acc[mt][nt][0], x1 = acc[mt][nt][1];
            float x2 = acc[mt][nt][2], x3 = acc[mt][nt][3];
            if (BIASM == 1) {
                float b0 = bias[col], b1 = bias[col + 1];
                x0 += b0; x1 += b1; x2 += b0; x3 += b1;
            } else if (BIASM == 2) {
                float br = bias[row], br8 = bias[row + 8];
                x0 += br; x1 += br; x2 += br8; x3 += br8;
            } else if (BIASM == 3) {
                float br = bias[row], br8 = bias[row + 8];
                x0 *= br; x1 *= br; x2 *= br8; x3 *= br8;
            }
            if (RELU) {
                x0 = fmaxf(x0, 0.f); x1 = fmaxf(x1, 0.f);
                x2 = fmaxf(x2, 0.f); x3 = fmaxf(x3, 0.f);
            }
            if (ROUND) { x0 = tf32f(x0); x1 = tf32f(x1); x2 = tf32f(x2); x3 = tf32f(x3); }
            *(float2*)(C + (size_t)row * ldc + col) = make_float2(x0, x1);
            *(float2*)(C + (size_t)(row + 8) * ldc + col) = make_float2(x2, x3);
        }
    }
}

// ================= cp-body: A [m][k], B [n][k], 3-stage cp.async =================
template<int BIASM, bool RELU, bool ROUND>
__device__ __forceinline__ void cp_body(const float* __restrict__ A, const float* __restrict__ B,
                                        const float* __restrict__ bias, float* __restrict__ C,
                                        int K, int lda, int ldb, int ldc,
                                        int bm, int bn, float* sm)
{
    const int tid  = threadIdx.x;
    const int lane = tid & 31, warp = tid >> 5;
    const int mw = warp & 1, nw = warp >> 1;
    const int g = lane >> 2, tg = lane & 3;

    const int r0 = tid >> 2,  kc = (tid & 3) << 2;
    const int r1 = r0 + 64;
    const float* gA0 = A + (size_t)(bm + r0) * lda + kc;
    const float* gA1 = A + (size_t)(bm + r1) * lda + kc;
    const float* gB0 = B + (size_t)(bn + r0) * ldb + kc;
    const float* gB1 = B + (size_t)(bn + r1) * ldb + kc;
    const int so = r0 * 16 + kc;
    const int s1 = r1 * 16 + kc;

    float acc[4][4][4];
#pragma unroll
    for (int i = 0; i < 4; i++)
#pragma unroll
        for (int j = 0; j < 4; j++)
#pragma unroll
            for (int r = 0; r < 4; r++) acc[i][j][r] = 0.f;

    const int nk = K >> 4;

    auto issue = [&](int t) {
        float* base = sm + (t % 3) * 4096;
        const size_t ko = (size_t)t << 4;
        cp16(base + so,        gA0 + ko);
        cp16(base + s1,        gA1 + ko);
        cp16(base + 2048 + so, gB0 + ko);
        cp16(base + 2048 + s1, gB1 + ko);
    };

    issue(0); CP_COMMIT();
    if (nk > 1) issue(1);
    CP_COMMIT();

    for (int t = 0; t < nk; t++) {
        if (t + 2 < nk) issue(t + 2);
        CP_COMMIT();
        CP_WAIT2();
        __syncthreads();

        const float* As = sm + (t % 3) * 4096;
        const float* Bs = As + 2048;

        float4 bf[4];
#pragma unroll
        for (int nt = 0; nt < 4; nt++)
            bf[nt] = *(const float4*)(Bs + (nw * 32 + nt * 8 + g) * 16 + 4 * tg);

#pragma unroll
        for (int mt = 0; mt < 4; mt++) {
            const int m0 = mw * 64 + mt * 16;
            float4 a0 = *(const float4*)(As + (m0 + g) * 16 + 4 * tg);
            float4 a1 = *(const float4*)(As + (m0 + g + 8) * 16 + 4 * tg);
            unsigned af0[4] = {__float_as_uint(a0.x), __float_as_uint(a1.x),
                               __float_as_uint(a0.y), __float_as_uint(a1.y)};
            unsigned af1[4] = {__float_as_uint(a0.z), __float_as_uint(a1.z),
                               __float_as_uint(a0.w), __float_as_uint(a1.w)};
#pragma unroll
            for (int nt = 0; nt < 4; nt++) {
                unsigned b0[2] = {__float_as_uint(bf[nt].x), __float_as_uint(bf[nt].y)};
                mma_tf32(acc[mt][nt], af0, b0);
            }
#pragma unroll
            for (int nt = 0; nt < 4; nt++) {
                unsigned b1[2] = {__float_as_uint(bf[nt].z), __float_as_uint(bf[nt].w)};
                mma_tf32(acc[mt][nt], af1, b1);
            }
        }
        __syncthreads();
    }

    epilogue<BIASM, RELU, ROUND>(acc, C, bias, bm, bn, ldc, mw, nw, g, tg);
}

// ================= kk-body: A [k][m], B [k][n], 2-stage cp.async =================
template<bool ROUND>
__device__ __forceinline__ void kk_body(const float* __restrict__ A, const float* __restrict__ B,
                                        float* __restrict__ C,
                                        int K, int lda, int ldb, int ldc,
                                        int bm, int bn, float* sm)
{
    const int tid  = threadIdx.x;
    const int lane = tid & 31, warp = tid >> 5;
    const int mw = warp & 1, nw = warp >> 1;
    const int g = lane >> 2, tg = lane & 3;

    const int STAGE = 2 * 16 * 136;

    const int kr0 = tid >> 5;
    const int kr1 = kr0 + 8;
    const int cc  = (tid & 31) << 2;
    const float* gA0 = A + (size_t)kr0 * lda + bm + cc;
    const float* gA1 = A + (size_t)kr1 * lda + bm + cc;
    const float* gB0 = B + (size_t)kr0 * ldb + bn + cc;
    const float* gB1 = B + (size_t)kr1 * ldb + bn + cc;
    const int soA0 = kr0 * 136 + cc, soA1 = kr1 * 136 + cc;

    float acc[4][4][4];
#pragma unroll
    for (int i = 0; i < 4; i++)
#pragma unroll
        for (int j = 0; j < 4; j++)
#pragma unroll
            for (int r = 0; r < 4; r++) acc[i][j][r] = 0.f;

    const int nk = K >> 4;

    auto issue = [&](int t) {
        float* base = sm + (t & 1) * STAGE;
        const size_t ko = (size_t)t * 16;
        cp16(base + soA0,              gA0 + ko * lda);
        cp16(base + soA1,              gA1 + ko * lda);
        cp16(base + 16 * 136 + soA0,   gB0 + ko * ldb);
        cp16(base + 16 * 136 + soA1,   gB1 + ko * ldb);
    };

    issue(0); CP_COMMIT();

    for (int t = 0; t < nk; t++) {
        if (t + 1 < nk) issue(t + 1);
        CP_COMMIT();
        CP_WAIT1();
        __syncthreads();

        const float* As = sm + (t & 1) * STAGE;
        const float* Bs = As + 16 * 136;

#pragma unroll
        for (int ks = 0; ks < 16; ks += 8) {
            unsigned bf[4][2];
#pragma unroll
            for (int nt = 0; nt < 4; nt++) {
                int n = nw * 32 + nt * 8 + g;
                bf[nt][0] = __float_as_uint(Bs[(ks + tg) * 136 + n]);
                bf[nt][1] = __float_as_uint(Bs[(ks + tg + 4) * 136 + n]);
            }
#pragma unroll
            for (int mt = 0; mt < 4; mt++) {
                int m0 = mw * 64 + mt * 16;
                unsigned af[4];
                af[0] = __float_as_uint(As[(ks + tg) * 136 + m0 + g]);
                af[1] = __float_as_uint(As[(ks + tg) * 136 + m0 + g + 8]);
                af[2] = __float_as_uint(As[(ks + tg + 4) * 136 + m0 + g]);
                af[3] = __float_as_uint(As[(ks + tg + 4) * 136 + m0 + g + 8]);
#pragma unroll
                for (int nt = 0; nt < 4; nt++)
                    mma_tf32(acc[mt][nt], af, bf[nt]);
            }
        }
        __syncthreads();
    }

    epilogue<0, false, ROUND>(acc, C, nullptr, bm, bn, ldc, mw, nw, g, tg);
}

// ================= energy kernel: e = l1 @ p1^T, epilogue writes exp weights =================
__global__ __launch_bounds__(256, 2)
void gemm_energy(const float* __restrict__ l12g, const float* __restrict__ p1g,
                 const float* __restrict__ inter,
                 float* __restrict__ att, float* __restrict__ epart)
{
    extern __shared__ float sm[];
    const int nx = blockIdx.x, my = blockIdx.y, z = blockIdx.z;
    const int zb = z >> 3, zh = z & 7;
    const float* A  = l12g + (size_t)zb * (LL_ * 2 * HD_) + zh * 128;   // lda 2048
    const float* B  = p1g  + (size_t)zb * (LP_ * HD_) + zh * 128;       // ldb 1024
    float* C = att + (size_t)zb * ((size_t)H_ * LL_ * LP_) + (size_t)zh * (LL_ * LP_);
    const float* ipt = inter + (size_t)zb * (LL_ * LP_);

    const int lda = 2048, ldb = 1024, ldc = 1024;
    const int bm = my * 128, bn = nx * 128;

    const int tid  = threadIdx.x;
    const int lane = tid & 31, warp = tid >> 5;
    const int mw = warp & 1, nw = warp >> 1;
    const int g = lane >> 2, tg = lane & 3;

    const int r0 = tid >> 2,  kc = (tid & 3) << 2;
    const int r1 = r0 + 64;
    const float* gA0 = A + (size_t)(bm + r0) * lda + kc;
    const float* gA1 = A + (size_t)(bm + r1) * lda + kc;
    const float* gB0 = B + (size_t)(bn + r0) * ldb + kc;
    const float* gB1 = B + (size_t)(bn + r1) * ldb + kc;
    const int so = r0 * 16 + kc;
    const int s1 = r1 * 16 + kc;

    float acc[4][4][4];
#pragma unroll
    for (int i = 0; i < 4; i++)
#pragma unroll
        for (int j = 0; j < 4; j++)
#pragma unroll
            for (int r = 0; r < 4; r++) acc[i][j][r] = 0.f;

    const int nk = 8;   // K=128

    auto issue = [&](int t) {
        float* base = sm + (t % 3) * 4096;
        const size_t ko = (size_t)t << 4;
        cp16(base + so,        gA0 + ko);
        cp16(base + s1,        gA1 + ko);
        cp16(base + 2048 + so, gB0 + ko);
        cp16(base + 2048 + s1, gB1 + ko);
    };

    issue(0); CP_COMMIT();
    issue(1); CP_COMMIT();

    for (int t = 0; t < nk; t++) {
        if (t + 2 < nk) issue(t + 2);
        CP_COMMIT();
        CP_WAIT2();
        __syncthreads();

        const float* As = sm + (t % 3) * 4096;
        const float* Bs = As + 2048;

        float4 bf[4];
#pragma unroll
        for (int nt = 0; nt < 4; nt++)
            bf[nt] = *(const float4*)(Bs + (nw * 32 + nt * 8 + g) * 16 + 4 * tg);

#pragma unroll
        for (int mt = 0; mt < 4; mt++) {
            const int m0 = mw * 64 + mt * 16;
            float4 a0 = *(const float4*)(As + (m0 + g) * 16 + 4 * tg);
            float4 a1 = *(const float4*)(As + (m0 + g + 8) * 16 + 4 * tg);
            unsigned af0[4] = {__float_as_uint(a0.x), __float_as_uint(a1.x),
                               __float_as_uint(a0.y), __float_as_uint(a1.y)};
            unsigned af1[4] = {__float_as_uint(a0.z), __float_as_uint(a1.z),
                               __float_as_uint(a0.w), __float_as_uint(a1.w)};
#pragma unroll
            for (int nt = 0; nt < 4; nt++) {
                unsigned b0[2] = {__float_as_uint(bf[nt].x), __float_as_uint(bf[nt].y)};
                mma_tf32(acc[mt][nt], af0, b0);
            }
#pragma unroll
            for (int nt = 0; nt < 4; nt++) {
                unsigned b1[2] = {__float_as_uint(bf[nt].z), __float_as_uint(bf[nt].w)};
                mma_tf32(acc[mt][nt], af1, b1);
            }
        }
        __syncthreads();
    }

    // ---- epilogue: exp weights + partial row sums (float2 inter loads) ----
    const float inv = 0.08838834764831845f;
    float rsum[4][2];
#pragma unroll
    for (int mt = 0; mt < 4; mt++) { rsum[mt][0] = 0.f; rsum[mt][1] = 0.f; }

#pragma unroll
    for (int mt = 0; mt < 4; mt++) {
#pragma unroll
        for (int nt = 0; nt < 4; nt++) {
            int row = bm + mw * 64 + mt * 16 + g;
            int col = bn + nw * 32 + nt * 8 + 2 * tg;
            float2 ia = *(const float2*)(ipt + (size_t)row * LP_ + col);
            float2 ib = *(const float2*)(ipt + (size_t)(row + 8) * LP_ + col);
            float w0 = tf32f(__expf(acc[mt][nt][0] * inv * ia.x));
            float w1 = tf32f(__expf(acc[mt][nt][1] * inv * ia.y));
            float w2 = tf32f(__expf(acc[mt][nt][2] * inv * ib.x));
            float w3 = tf32f(__expf(acc[mt][nt][3] * inv * ib.y));
            *(float2*)(C + (size_t)row * ldc + col) = make_float2(w0, w1);
            *(float2*)(C + (size_t)(row + 8) * ldc + col) = make_float2(w2, w3);
            rsum[mt][0] += w0 + w1;
            rsum[mt][1] += w2 + w3;
        }
    }

#pragma unroll
    for (int mt = 0; mt < 4; mt++) {
#pragma unroll
        for (int r = 0; r < 2; r++) {
            float v = rsum[mt][r];
            v += __shfl_xor_sync(0xffffffffu, v, 1);
            v += __shfl_xor_sync(0xffffffffu, v, 2);
            if (tg == 0)
                sm[nw * 128 + mw * 64 + mt * 16 + g + r * 8] = v;
        }
    }
    __syncthreads();
    if (tid < 128) {
        float s = sm[tid] + sm[128 + tid] + sm[256 + tid] + sm[384 + tid];
        epart[((size_t)z * 256 + bm + tid) * 8 + nx] = s;
    }
}

// reciprocal row sums
__global__ void reduce_rs(const float* __restrict__ epart, float* __restrict__ rs)
{
    int i = blockIdx.x * 256 + threadIdx.x;
    const float* p = epart + (size_t)i * 8;
    float s = p[0] + p[1] + p[2] + p[3] + p[4] + p[5] + p[6] + p[7];
    rs[i] = 1.0f / s;
}

// l2s[b][l][h*128+d] = tf32( l2 * rs[b,h,l] )
__global__ void scale_l2(const float4* __restrict__ l12v, const float* __restrict__ rs,
                         float4* __restrict__ l2s)
{
    int i = blockIdx.x * 256 + threadIdx.x;     // 1048576 -> 4096 blocks
    int hd4 = i & 255, l = (i >> 8) & 255, b = i >> 16;
    int h = hd4 >> 5;
    float r = rs[((size_t)b * 8 + h) * 256 + l];
    float4 v = l12v[(size_t)b * (LL_ * 2 * HD_ / 4) + (size_t)l * (2 * HD_ / 4) + HD_ / 4 + hd4];
    l2s[(size_t)b * (LL_ * HD_ / 4) + (size_t)l * (HD_ / 4) + hd4] =
        make_float4(tf32f(v.x * r), tf32f(v.y * r), tf32f(v.z * r), tf32f(v.w * r));
}

// ================= global kernels =================
__global__ __launch_bounds__(256, 2)
void gemm_proj(const float* __restrict__ ligr, const float* __restrict__ protr,
               const float* __restrict__ w, const float* __restrict__ bb,
               const float* __restrict__ bp1, const float* __restrict__ bp2,
               float* __restrict__ l12, float* __restrict__ p1, float* __restrict__ p2t)
{
    extern __shared__ float sm[];
    int id = blockIdx.x;
    if (id < 512) {
        int my = id >> 4, nx = id & 15;
        cp_body<1, true, true>(ligr, w + OW_L1, bb, l12,
                               128, 128, 128, 2048, my * 128, nx * 128, sm);
    } else if (id < 1536) {
        int id2 = id - 512;
        int my = id2 >> 3, nx = id2 & 7;
        cp_body<1, true, true>(protr, w + OW_P1, bp1, p1,
                               128, 128, 128, 1024, my * 128, nx * 128, sm);
    } else {
        int id2 = id - 1536;
        int zb = id2 >> 6, rem = id2 & 63;
        int my = rem >> 3, nx = rem & 7;
        cp_body<2, true, true>(w + OW_P2, protr + (size_t)zb * LP_ * HID_, bp2,
                               p2t + (size_t)zb * HD_ * LP_,
                               128, 128, 128, 1024, my * 128, nx * 128, sm);
    }
}

template<int BIASM, bool RELU, bool ROUND>
__global__ __launch_bounds__(256, 2)
void gemm_cp2(const float* __restrict__ A0, const float* __restrict__ B0,
              const float* __restrict__ b0, float* __restrict__ C0, int n0,
              const float* __restrict__ A1, const float* __restrict__ B1,
              const float* __restrict__ b1, float* __restrict__ C1,
              int K, int lda, int ldb, int ldc)
{
    extern __shared__ float sm[];
    int id = blockIdx.x;
    if (id < n0)
        cp_body<BIASM, RELU, ROUND>(A0, B0, b0, C0, K, lda, ldb, ldc, id * 128, 0, sm);
    else
        cp_body<BIASM, RELU, ROUND>(A1, B1, b1, C1, K, lda, ldb, ldc, (id - n0) * 128, 0, sm);
}

// fused attention-output (round-13 ordering: long lig3 CTAs first, then prot3)
__global__ __launch_bounds__(256, 2)
void gemm_av(const float* __restrict__ att, const float* __restrict__ p2t,
             const float* __restrict__ l2s, const float* __restrict__ rs,
             float* __restrict__ lig3, float* __restrict__ prot3)
{
    extern __shared__ float sm[];
    int id = blockIdx.x;
    if (id < 256) {
        int z = id & 127, my = id >> 7;
        int zb = z >> 3, zh = z & 7;
        const float* A = att + (size_t)zb * ((size_t)H_ * LL_ * LP_) + (size_t)zh * (LL_ * LP_);
        const float* Bp = p2t + (size_t)zb * (HD_ * LP_) + (size_t)zh * (128 * LP_);
        float* C = lig3 + (size_t)zb * (LL_ * HD_) + zh * 128;
        const float* rsz = rs + (size_t)z * 256;
        cp_body<3, false, true>(A, Bp, rsz, C, 1024, LP_, LP_, HD_, my * 128, 0, sm);
    } else {
        int id2 = id - 256;
        int z = id2 >> 3, my = id2 & 7;
        int zb = z >> 3, zh = z & 7;
        const float* A = att + (size_t)zb * ((size_t)H_ * LL_ * LP_) + (size_t)zh * (LL_ * LP_);
        const float* Bl = l2s + (size_t)zb * (LL_ * HD_) + zh * 128;
        float* C = prot3 + (size_t)zb * (LP_ * HD_) + zh * 128;
        kk_body<true>(A, Bl, C, 256, LP_, HD_, HD_, my * 128, 0, sm);
    }
}

// ---------------- merged preprocessing ----------------
// 131072 + 524288 + 2048 = 657408 threads -> 2568 blocks of 256
__global__ void preproc(const float4* __restrict__ lig, const float4* __restrict__ prot,
                        const float* __restrict__ bl1, const float* __restrict__ bl2,
                        float4* __restrict__ ligr, float4* __restrict__ protr,
                        float4* __restrict__ lcat, float4* __restrict__ pcat,
                        float* __restrict__ bb)
{
    int i = blockIdx.x * 256 + threadIdx.x;
    const int n1 = B_ * LL_ * HID_ / 4;   // 131072
    const int n2 = B_ * LP_ * HID_ / 4;   // 524288
    if (i < n1) {
        float4 v = lig[i];
        v = make_float4(tf32f(v.x), tf32f(v.y), tf32f(v.z), tf32f(v.w));
        ligr[i] = v;
        int r = i >> 5, c = i & 31;
        lcat[(size_t)r * 64 + 32 + c] = v;
    } else if (i < n1 + n2) {
        int j = i - n1;
        float4 v = prot[j];
        v = make_float4(tf32f(v.x), tf32f(v.y), tf32f(v.z), tf32f(v.w));
        protr[j] = v;
        int r = j >> 5, c = j & 31;
        pcat[(size_t)r * 64 + 32 + c] = v;
    } else {
        int j = i - n1 - n2;
        if (j < 1024) bb[j] = bl1[j];
        else if (j < 2048) bb[j] = bl2[j - 1024];
    }
}

__global__ void transpose_round8(const float* w0, const float* w1, const float* w2,
                                 const float* w3, const float* w4, const float* w5,
                                 const float* w6, const float* w7, float* wb)
{
    const float* ins[8] = {w0, w1, w2, w3, w4, w5, w6, w7};
    const int Rs[8]   = {128, 128, 128, 128, 1024, 1024, 256, 256};
    const int Cs[8]   = {1024, 1024, 1024, 1024, 128, 128, 128, 128};
    const int offs[8] = {OW_L1, OW_L2, OW_P1, OW_P2, OW_11, OW_21, OW_12, OW_22};
    int zi = blockIdx.z;
    int R = Rs[zi], C = Cs[zi];
    int bx = blockIdx.x * 32, by = blockIdx.y * 32;
    if (bx >= C || by >= R) return;
    const float* in = ins[zi];
    float* out = wb + offs[zi];

    __shared__ float t[32][33];
    int tx = threadIdx.x, ty = threadIdx.y;
#pragma unroll
    for (int j = 0; j < 32; j += 8)
        t[ty + j][tx] = in[(size_t)(by + ty + j) * C + bx + tx];
    __syncthreads();
#pragma unroll
    for (int j = 0; j < 32; j += 8)
        out[(size_t)(bx + ty + j) * R + by + tx] = tf32f(t[tx][ty + j]);
}

// ---------------- launcher ----------------
extern "C" void kernel_launch(void* const* d_in, const int* in_sizes, int n_in,
                              void* d_out, int out_size)
{
    const float* ligand = (const float*)d_in[0];
    const float* prot   = (const float*)d_in[1];
    const float* inter  = (const float*)d_in[2];
    const float* Wl1 = (const float*)d_in[3];  const float* bl1 = (const float*)d_in[4];
    const float* Wl2 = (const float*)d_in[5];  const float* bl2 = (const float*)d_in[6];
    const float* Wp1 = (const float*)d_in[7];  const float* bp1 = (const float*)d_in[8];
    const float* Wp2 = (const float*)d_in[9];  const float* bp2 = (const float*)d_in[10];
    const float* W11 = (const float*)d_in[11]; const float* b11 = (const float*)d_in[12];
    const float* W12 = (const float*)d_in[13]; const float* b12 = (const float*)d_in[14];
    const float* W21 = (const float*)d_in[15]; const float* b21 = (const float*)d_in[16];
    const float* W22 = (const float*)d_in[17]; const float* b22 = (const float*)d_in[18];

    float* out_lig  = (float*)d_out;
    float* out_prot = out_lig + (size_t)B_ * LL_ * HID_;

    float *l12, *p1, *p2t, *att, *lig3, *prot3, *lcat, *pcat, *ligr, *protr, *w, *bb;
    float *l2s, *epart, *rs;
    cudaGetSymbolAddress((void**)&l12, g_l12);
    cudaGetSymbolAddress((void**)&p1, g_p1);
    cudaGetSymbolAddress((void**)&p2t, g_p2t);
    cudaGetSymbolAddress((void**)&att, g_att);
    cudaGetSymbolAddress((void**)&lig3, g_lig3);
    cudaGetSymbolAddress((void**)&prot3, g_prot3);
    cudaGetSymbolAddress((void**)&lcat, g_ligcat);
    cudaGetSymbolAddress((void**)&pcat, g_protcat);
    cudaGetSymbolAddress((void**)&ligr, g_ligr);
    cudaGetSymbolAddress((void**)&protr, g_protr);
    cudaGetSymbolAddress((void**)&w, g_w);
    cudaGetSymbolAddress((void**)&bb, g_b12);
    cudaGetSymbolAddress((void**)&l2s, g_l2s);
    cudaGetSymbolAddress((void**)&epart, g_epart);
    cudaGetSymbolAddress((void**)&rs, g_rs);

    dim3 blk(256);
    const int SMEM = 49152;

    // --- preprocessing ---
    preproc<<<2568, 256>>>((const float4*)ligand, (const float4*)prot, bl1, bl2,
                           (float4*)ligr, (float4*)protr,
                           (float4*)lcat, (float4*)pcat, bb);
    transpose_round8<<<dim3(32, 32, 8), dim3(32, 8)>>>(
        Wl1, Wl2, Wp1, Wp2, W11, W21, W12, W22, w);

    // --- all three projections in one 2560-CTA launch ---
    gemm_proj<<<2560, blk, SMEM>>>(ligr, protr, w, bb, bp1, bp2, l12, p1, p2t);

    // --- energy with fused exp/gating epilogue + partial row sums ---
    gemm_energy<<<dim3(8, 2, 128), blk, SMEM>>>(l12, p1, inter, att, epart);

    // --- reciprocal row sums + scaled l2 ---
    reduce_rs<<<128, 256>>>(epart, rs);
    scale_l2<<<4096, 256>>>((const float4*)l12, rs, (float4*)l2s);

    // --- fused lig3 + prot3 (1280 CTAs, long CTAs first) ---
    gemm_av<<<1280, blk, SMEM>>>(att, p2t, l2s, rs, lig3, prot3);

    // --- paired branch MLP stage 1 ---
    gemm_cp2<1,false,true><<<160, blk, SMEM>>>(
        lig3,  w + OW_11, b11, lcat, 32,
        prot3, w + OW_21, b21, pcat,
        1024, 1024, 1024, 256);

    // --- paired branch MLP stage 2 ---
    gemm_cp2<1,true,false><<<160, blk, SMEM>>>(
        lcat, w + OW_12, b12, out_lig, 32,
        pcat, w + OW_22, b22, out_prot,
        256, 256, 256, 128);
}

// round 16
// speedup vs baseline: 1.1156x; 1.0368x over previous
#include <cuda_runtime.h>
#include <cuda_bf16.h>

#define B_    16
#define LL_   256
#define LP_   1024
#define HID_  128
#define H_    8
#define HD_   1024

// ---------------- scratch ----------------
__device__ float g_l12[B_ * LL_ * 2 * HD_];             // [b][l][l1|l2]
__device__ float g_p1[B_ * LP_ * HD_];
__device__ float g_p2t[B_ * HD_ * LP_];                 // [b][h*128+d][p]
__device__ __nv_bfloat16 g_att[(size_t)B_ * H_ * LL_ * LP_];  // unnormalized exp weights (bf16)
__device__ float g_lig3[B_ * LL_ * HD_];
__device__ float g_prot3[B_ * LP_ * HD_];
__device__ float g_ligcat[B_ * LL_ * 2 * HID_];
__device__ float g_protcat[B_ * LP_ * 2 * HID_];
__device__ float g_ligr[B_ * LL_ * HID_];
__device__ float g_protr[B_ * LP_ * HID_];
__device__ float g_l2s[B_ * LL_ * HD_];                 // l2 scaled by row reciprocal sums
__device__ float g_epart[B_ * H_ * LL_ * 8];            // per-CTA-column partial row sums
__device__ float g_rs[B_ * H_ * LL_];                   // reciprocal row sums
__device__ float g_w[851968];
__device__ float g_b12[2048];

#define OW_L1  0
#define OW_L2  131072
#define OW_P1  262144
#define OW_P2  393216
#define OW_11  524288
#define OW_21  655360
#define OW_12  786432
#define OW_22  819200

// ---------------- helpers ----------------
__device__ __forceinline__ unsigned tf32_of(float f) {
    unsigned r;
    asm("cvt.rna.tf32.f32 %0, %1;" : "=r"(r) : "f"(f));
    return r;
}
__device__ __forceinline__ float tf32f(float f) { return __uint_as_float(tf32_of(f)); }

__device__ __forceinline__ void mma_tf32(float c[4], const unsigned a[4], const unsigned b[2]) {
    asm volatile(
        "mma.sync.aligned.m16n8k8.row.col.f32.tf32.tf32.f32 "
        "{%0,%1,%2,%3}, {%4,%5,%6,%7}, {%8,%9}, {%0,%1,%2,%3};"
        : "+f"(c[0]), "+f"(c[1]), "+f"(c[2]), "+f"(c[3])
        : "r"(a[0]), "r"(a[1]), "r"(a[2]), "r"(a[3]), "r"(b[0]), "r"(b[1]));
}

__device__ __forceinline__ void cp16(float* sm, const void* gm) {
    unsigned a = (unsigned)__cvta_generic_to_shared(sm);
    asm volatile("cp.async.cg.shared.global [%0], [%1], 16;" :: "r"(a), "l"(gm));
}
#define CP_COMMIT() asm volatile("cp.async.commit_group;" ::: "memory")
#define CP_WAIT2()  asm volatile("cp.async.wait_group 2;" ::: "memory")
#define CP_WAIT1()  asm volatile("cp.async.wait_group 1;" ::: "memory")

// shared epilogue. BIASM: 0 none, 1 bias[col], 2 bias[row], 3 row-scale by bias[row]
template<int BIASM, bool RELU, bool ROUND>
__device__ __forceinline__ void epilogue(float acc[4][4][4], float* C, const float* bias,
                                         int bm, int bn, int ldc, int mw, int nw, int g, int tg)
{
#pragma unroll
    for (int mt = 0; mt < 4; mt++) {
#pragma unroll
        for (int nt = 0; nt < 4; nt++) {
            int row = bm + mw * 64 + mt * 16 + g;
            int col = bn + nw * 32 + nt * 8 + 2 * tg;
            float x0 = acc[mt][nt][0], x1 = acc[mt][nt][1];
            float x2 = acc[mt][nt][2], x3 = acc[mt][nt][3];
            if (BIASM == 1) {
                float b0 = bias[col], b1 = bias[col + 1];
                x0 += b0; x1 += b1; x2 += b0; x3 += b1;
            } else if (BIASM == 2) {
                float br = bias[row], br8 = bias[row + 8];
                x0 += br; x1 += br; x2 += br8; x3 += br8;
            } else if (BIASM == 3) {
                float br = bias[row], br8 = bias[row + 8];
                x0 *= br; x1 *= br; x2 *= br8; x3 *= br8;
            }
            if (RELU) {
                x0 = fmaxf(x0, 0.f); x1 = fmaxf(x1, 0.f);
                x2 = fmaxf(x2, 0.f); x3 = fmaxf(x3, 0.f);
            }
            if (ROUND) { x0 = tf32f(x0); x1 = tf32f(x1); x2 = tf32f(x2); x3 = tf32f(x3); }
            *(float2*)(C + (size_t)row * ldc + col) = make_float2(x0, x1);
            *(float2*)(C + (size_t)(row + 8) * ldc + col) = make_float2(x2, x3);
        }
    }
}

// ================= cp-body: A [m][k] fp32, B [n][k] fp32, 3-stage cp.async =================
template<int BIASM, bool RELU, bool ROUND>
__device__ __forceinline__ void cp_body(const float* __restrict__ A, const float* __restrict__ B,
                                        const float* __restrict__ bias, float* __restrict__ C,
                                        int K, int lda, int ldb, int ldc,
                                        int bm, int bn, float* sm)
{
    const int tid  = threadIdx.x;
    const int lane = tid & 31, warp = tid >> 5;
    const int mw = warp & 1, nw = warp >> 1;
    const int g = lane >> 2, tg = lane & 3;

    const int r0 = tid >> 2,  kc = (tid & 3) << 2;
    const int r1 = r0 + 64;
    const float* gA0 = A + (size_t)(bm + r0) * lda + kc;
    const float* gA1 = A + (size_t)(bm + r1) * lda + kc;
    const float* gB0 = B + (size_t)(bn + r0) * ldb + kc;
    const float* gB1 = B + (size_t)(bn + r1) * ldb + kc;
    const int so = r0 * 16 + kc;
    const int s1 = r1 * 16 + kc;

    float acc[4][4][4];
#pragma unroll
    for (int i = 0; i < 4; i++)
#pragma unroll
        for (int j = 0; j < 4; j++)
#pragma unroll
            for (int r = 0; r < 4; r++) acc[i][j][r] = 0.f;

    const int nk = K >> 4;

    auto issue = [&](int t) {
        float* base = sm + (t % 3) * 4096;
        const size_t ko = (size_t)t << 4;
        cp16(base + so,        gA0 + ko);
        cp16(base + s1,        gA1 + ko);
        cp16(base + 2048 + so, gB0 + ko);
        cp16(base + 2048 + s1, gB1 + ko);
    };

    issue(0); CP_COMMIT();
    if (nk > 1) issue(1);
    CP_COMMIT();

    for (int t = 0; t < nk; t++) {
        if (t + 2 < nk) issue(t + 2);
        CP_COMMIT();
        CP_WAIT2();
        __syncthreads();

        const float* As = sm + (t % 3) * 4096;
        const float* Bs = As + 2048;

        float4 bf[4];
#pragma unroll
        for (int nt = 0; nt < 4; nt++)
            bf[nt] = *(const float4*)(Bs + (nw * 32 + nt * 8 + g) * 16 + 4 * tg);

#pragma unroll
        for (int mt = 0; mt < 4; mt++) {
            const int m0 = mw * 64 + mt * 16;
            float4 a0 = *(const float4*)(As + (m0 + g) * 16 + 4 * tg);
            float4 a1 = *(const float4*)(As + (m0 + g + 8) * 16 + 4 * tg);
            unsigned af0[4] = {__float_as_uint(a0.x), __float_as_uint(a1.x),
                               __float_as_uint(a0.y), __float_as_uint(a1.y)};
            unsigned af1[4] = {__float_as_uint(a0.z), __float_as_uint(a1.z),
                               __float_as_uint(a0.w), __float_as_uint(a1.w)};
#pragma unroll
            for (int nt = 0; nt < 4; nt++) {
                unsigned b0[2] = {__float_as_uint(bf[nt].x), __float_as_uint(bf[nt].y)};
                mma_tf32(acc[mt][nt], af0, b0);
            }
#pragma unroll
            for (int nt = 0; nt < 4; nt++) {
                unsigned b1[2] = {__float_as_uint(bf[nt].z), __float_as_uint(bf[nt].w)};
                mma_tf32(acc[mt][nt], af1, b1);
            }
        }
        __syncthreads();
    }

    epilogue<BIASM, RELU, ROUND>(acc, C, bias, bm, bn, ldc, mw, nw, g, tg);
}

// ========== cp_bf_body: A [m][k] BF16, B [n][k] fp32, 3-stage cp.async ==========
// A tile 128x16 bf16 = 1024 words; B tile 128x16 fp32 = 2048 floats; stage 3072 floats.
template<int BIASM, bool RELU, bool ROUND>
__device__ __forceinline__ void cp_bf_body(const __nv_bfloat16* __restrict__ A,
                                           const float* __restrict__ B,
                                           const float* __restrict__ bias, float* __restrict__ C,
                                           int K, int lda, int ldb, int ldc,
                                           int bm, int bn, float* sm)
{
    const int tid  = threadIdx.x;
    const int lane = tid & 31, warp = tid >> 5;
    const int mw = warp & 1, nw = warp >> 1;
    const int g = lane >> 2, tg = lane & 3;

    const int SF = 3072;

    // A: 256 chunks of 16B (8 bf16) -> 1 per thread
    const int ar = tid >> 1, ah = tid & 1;
    const __nv_bfloat16* gA = A + (size_t)(bm + ar) * lda + ah * 8;
    const int soA = ar * 8 + ah * 4;   // word (float) offset in A region
    // B: 512 chunks -> 2 per thread
    const int r0 = tid >> 2, kc = (tid & 3) << 2, r1 = r0 + 64;
    const float* gB0 = B + (size_t)(bn + r0) * ldb + kc;
    const float* gB1 = B + (size_t)(bn + r1) * ldb + kc;
    const int soB0 = 1024 + r0 * 16 + kc;
    const int soB1 = 1024 + r1 * 16 + kc;

    float acc[4][4][4];
#pragma unroll
    for (int i = 0; i < 4; i++)
#pragma unroll
        for (int j = 0; j < 4; j++)
#pragma unroll
            for (int r = 0; r < 4; r++) acc[i][j][r] = 0.f;

    const int nk = K >> 4;

    auto issue = [&](int t) {
        float* base = sm + (t % 3) * SF;
        cp16(base + soA,  gA + (size_t)t * 16);
        cp16(base + soB0, gB0 + (size_t)t * 16);
        cp16(base + soB1, gB1 + (size_t)t * 16);
    };

    issue(0); CP_COMMIT();
    if (nk > 1) issue(1);
    CP_COMMIT();

    for (int t = 0; t < nk; t++) {
        if (t + 2 < nk) issue(t + 2);
        CP_COMMIT();
        CP_WAIT2();
        __syncthreads();

        const unsigned* Au = (const unsigned*)(sm + (t % 3) * SF);
        const float* Bs = sm + (t % 3) * SF + 1024;

        float4 bf[4];
#pragma unroll
        for (int nt = 0; nt < 4; nt++)
            bf[nt] = *(const float4*)(Bs + (nw * 32 + nt * 8 + g) * 16 + 4 * tg);

#pragma unroll
        for (int mt = 0; mt < 4; mt++) {
            const int m0 = mw * 64 + mt * 16;
            uint2 wa0 = *(const uint2*)(Au + (m0 + g) * 8 + 2 * tg);       // row m0+g,  k 4tg..4tg+3
            uint2 wa1 = *(const uint2*)(Au + (m0 + g + 8) * 8 + 2 * tg);   // row m0+g+8
            unsigned af0[4] = {wa0.x << 16, wa1.x << 16,
                               wa0.x & 0xFFFF0000u, wa1.x & 0xFFFF0000u};
            unsigned af1[4] = {wa0.y << 16, wa1.y << 16,
                               wa0.y & 0xFFFF0000u, wa1.y & 0xFFFF0000u};
#pragma unroll
            for (int nt = 0; nt < 4; nt++) {
                unsigned b0[2] = {__float_as_uint(bf[nt].x), __float_as_uint(bf[nt].y)};
                mma_tf32(acc[mt][nt], af0, b0);
            }
#pragma unroll
            for (int nt = 0; nt < 4; nt++) {
                unsigned b1[2] = {__float_as_uint(bf[nt].z), __float_as_uint(bf[nt].w)};
                mma_tf32(acc[mt][nt], af1, b1);
            }
        }
        __syncthreads();
    }

    epilogue<BIASM, RELU, ROUND>(acc, C, bias, bm, bn, ldc, mw, nw, g, tg);
}

// ========== kk_bf_body: A [k][m] BF16, B [k][n] fp32, 2-stage cp.async ==========
// A tile 16x128 bf16, row stride 72 words (conflict-free); B tile 16x136-stride floats.
template<bool ROUND>
__device__ __forceinline__ void kk_bf_body(const __nv_bfloat16* __restrict__ A,
                                           const float* __restrict__ B, float* __restrict__ C,
                                           int K, int lda, int ldb, int ldc,
                                           int bm, int bn, float* sm)
{
    const int tid  = threadIdx.x;
    const int lane = tid & 31, warp = tid >> 5;
    const int mw = warp & 1, nw = warp >> 1;
    const int g = lane >> 2, tg = lane & 3;

    const int SF = 1152 + 2176;   // 3328 floats per stage

    // A: 256 chunks of 16B -> 1 per thread
    const int akr = tid >> 4;          // k row 0..15
    const int ac16 = tid & 15;         // 16B chunk in row
    const __nv_bfloat16* gA = A + (size_t)akr * lda + bm + ac16 * 8;
    const int soA = akr * 72 + ac16 * 4;
    // B: 2 per thread
    const int kr0 = tid >> 5, kr1 = kr0 + 8, cc = (tid & 31) << 2;
    const float* gB0 = B + (size_t)kr0 * ldb + bn + cc;
    const float* gB1 = B + (size_t)kr1 * ldb + bn + cc;
    const int soB0 = 1152 + kr0 * 136 + cc;
    const int soB1 = 1152 + kr1 * 136 + cc;

    float acc[4][4][4];
#pragma unroll
    for (int i = 0; i < 4; i++)
#pragma unroll
        for (int j = 0; j < 4; j++)
#pragma unroll
            for (int r = 0; r < 4; r++) acc[i][j][r] = 0.f;

    const int nk = K >> 4;

    auto issue = [&](int t) {
        float* base = sm + (t & 1) * SF;
        const size_t ko = (size_t)t * 16;
        cp16(base + soA,  gA + ko * lda);
        cp16(base + soB0, gB0 + ko * ldb);
        cp16(base + soB1, gB1 + ko * ldb);
    };

    issue(0); CP_COMMIT();

    for (int t = 0; t < nk; t++) {
        if (t + 1 < nk) issue(t + 1);
        CP_COMMIT();
        CP_WAIT1();
        __syncthreads();

        const unsigned* Au = (const unsigned*)(sm + (t & 1) * SF);
        const float* Bs = sm + (t & 1) * SF + 1152;

#pragma unroll
        for (int ks = 0; ks < 16; ks += 8) {
            unsigned bfr[4][2];
#pragma unroll
            for (int nt = 0; nt < 4; nt++) {
                int n = nw * 32 + nt * 8 + g;
                bfr[nt][0] = __float_as_uint(Bs[(ks + tg) * 136 + n]);
                bfr[nt][1] = __float_as_uint(Bs[(ks + tg + 4) * 136 + n]);
            }
#pragma unroll
            for (int mt = 0; mt < 4; mt++) {
                int m0 = mw * 64 + mt * 16;
                int wof = (m0 >> 1) + (g >> 1);
                bool hi = (g & 1);
                unsigned w00 = Au[(ks + tg) * 72 + wof];
                unsigned w08 = Au[(ks + tg) * 72 + wof + 4];
                unsigned w40 = Au[(ks + tg + 4) * 72 + wof];
                unsigned w48 = Au[(ks + tg + 4) * 72 + wof + 4];
                unsigned af[4];
                af[0] = hi ? (w00 & 0xFFFF0000u) : (w00 << 16);
                af[1] = hi ? (w08 & 0xFFFF0000u) : (w08 << 16);
                af[2] = hi ? (w40 & 0xFFFF0000u) : (w40 << 16);
                af[3] = hi ? (w48 & 0xFFFF0000u) : (w48 << 16);
#pragma unroll
                for (int nt = 0; nt < 4; nt++)
                    mma_tf32(acc[mt][nt], af, bfr[nt]);
            }
        }
        __syncthreads();
    }

    epilogue<0, false, ROUND>(acc, C, nullptr, bm, bn, ldc, mw, nw, g, tg);
}

// ================= energy kernel: epilogue writes bf16 exp weights =================
__global__ __launch_bounds__(256, 2)
void gemm_energy(const float* __restrict__ l12g, const float* __restrict__ p1g,
                 const float* __restrict__ inter,
                 __nv_bfloat16* __restrict__ att, float* __restrict__ epart)
{
    extern __shared__ float sm[];
    const int nx = blockIdx.x, my = blockIdx.y, z = blockIdx.z;
    const int zb = z >> 3, zh = z & 7;
    const float* A  = l12g + (size_t)zb * (LL_ * 2 * HD_) + zh * 128;   // lda 2048
    const float* B  = p1g  + (size_t)zb * (LP_ * HD_) + zh * 128;       // ldb 1024
    __nv_bfloat16* C = att + (size_t)zb * ((size_t)H_ * LL_ * LP_) + (size_t)zh * (LL_ * LP_);
    const float* ipt = inter + (size_t)zb * (LL_ * LP_);

    const int lda = 2048, ldb = 1024, ldc = 1024;
    const int bm = my * 128, bn = nx * 128;

    const int tid  = threadIdx.x;
    const int lane = tid & 31, warp = tid >> 5;
    const int mw = warp & 1, nw = warp >> 1;
    const int g = lane >> 2, tg = lane & 3;

    const int r0 = tid >> 2,  kc = (tid & 3) << 2;
    const int r1 = r0 + 64;
    const float* gA0 = A + (size_t)(bm + r0) * lda + kc;
    const float* gA1 = A + (size_t)(bm + r1) * lda + kc;
    const float* gB0 = B + (size_t)(bn + r0) * ldb + kc;
    const float* gB1 = B + (size_t)(bn + r1) * ldb + kc;
    const int so = r0 * 16 + kc;
    const int s1 = r1 * 16 + kc;

    float acc[4][4][4];
#pragma unroll
    for (int i = 0; i < 4; i++)
#pragma unroll
        for (int j = 0; j < 4; j++)
#pragma unroll
            for (int r = 0; r < 4; r++) acc[i][j][r] = 0.f;

    const int nk = 8;   // K=128

    auto issue = [&](int t) {
        float* base = sm + (t % 3) * 4096;
        const size_t ko = (size_t)t << 4;
        cp16(base + so,        gA0 + ko);
        cp16(base + s1,        gA1 + ko);
        cp16(base + 2048 + so, gB0 + ko);
        cp16(base + 2048 + s1, gB1 + ko);
    };

    issue(0); CP_COMMIT();
    issue(1); CP_COMMIT();

    for (int t = 0; t < nk; t++) {
        if (t + 2 < nk) issue(t + 2);
        CP_COMMIT();
        CP_WAIT2();
        __syncthreads();

        const float* As = sm + (t % 3) * 4096;
        const float* Bs = As + 2048;

        float4 bf[4];
#pragma unroll
        for (int nt = 0; nt < 4; nt++)
            bf[nt] = *(const float4*)(Bs + (nw * 32 + nt * 8 + g) * 16 + 4 * tg);

#pragma unroll
        for (int mt = 0; mt < 4; mt++) {
            const int m0 = mw * 64 + mt * 16;
            float4 a0 = *(const float4*)(As + (m0 + g) * 16 + 4 * tg);
            float4 a1 = *(const float4*)(As + (m0 + g + 8) * 16 + 4 * tg);
            unsigned af0[4] = {__float_as_uint(a0.x), __float_as_uint(a1.x),
                               __float_as_uint(a0.y), __float_as_uint(a1.y)};
            unsigned af1[4] = {__float_as_uint(a0.z), __float_as_uint(a1.z),
                               __float_as_uint(a0.w), __float_as_uint(a1.w)};
#pragma unroll
            for (int nt = 0; nt < 4; nt++) {
                unsigned b0[2] = {__float_as_uint(bf[nt].x), __float_as_uint(bf[nt].y)};
                mma_tf32(acc[mt][nt], af0, b0);
            }
#pragma unroll
            for (int nt = 0; nt < 4; nt++) {
                unsigned b1[2] = {__float_as_uint(bf[nt].z), __float_as_uint(bf[nt].w)};
                mma_tf32(acc[mt][nt], af1, b1);
            }
        }
        __syncthreads();
    }

    // ---- epilogue: bf16 exp weights + partial row sums (sums of STORED values) ----
    const float inv = 0.08838834764831845f;
    float rsum[4][2];
#pragma unroll
    for (int mt = 0; mt < 4; mt++) { rsum[mt][0] = 0.f; rsum[mt][1] = 0.f; }

#pragma unroll
    for (int mt = 0; mt < 4; mt++) {
#pragma unroll
        for (int nt = 0; nt < 4; nt++) {
            int row = bm + mw * 64 + mt * 16 + g;
            int col = bn + nw * 32 + nt * 8 + 2 * tg;
            float2 ia = *(const float2*)(ipt + (size_t)row * LP_ + col);
            float2 ib = *(const float2*)(ipt + (size_t)(row + 8) * LP_ + col);
            __nv_bfloat162 p01, p23;
            p01.x = __float2bfloat16_rn(__expf(acc[mt][nt][0] * inv * ia.x));
            p01.y = __float2bfloat16_rn(__expf(acc[mt][nt][1] * inv * ia.y));
            p23.x = __float2bfloat16_rn(__expf(acc[mt][nt][2] * inv * ib.x));
            p23.y = __float2bfloat16_rn(__expf(acc[mt][nt][3] * inv * ib.y));
            *(__nv_bfloat162*)(C + (size_t)row * ldc + col) = p01;
            *(__nv_bfloat162*)(C + (size_t)(row + 8) * ldc + col) = p23;
            rsum[mt][0] += __bfloat162float(p01.x) + __bfloat162float(p01.y);
            rsum[mt][1] += __bfloat162float(p23.x) + __bfloat162float(p23.y);
        }
    }

#pragma unroll
    for (int mt = 0; mt < 4; mt++) {
#pragma unroll
        for (int r = 0; r < 2; r++) {
            float v = rsum[mt][r];
            v += __shfl_xor_sync(0xffffffffu, v, 1);
            v += __shfl_xor_sync(0xffffffffu, v, 2);
            if (tg == 0)
                sm[nw * 128 + mw * 64 + mt * 16 + g + r * 8] = v;
        }
    }
    __syncthreads();
    if (tid < 128) {
        float s = sm[tid] + sm[128 + tid] + sm[256 + tid] + sm[384 + tid];
        epart[((size_t)z * 256 + bm + tid) * 8 + nx] = s;
    }
}

// reciprocal row sums
__global__ void reduce_rs(const float* __restrict__ epart, float* __restrict__ rs)
{
    int i = blockIdx.x * 256 + threadIdx.x;
    const float* p = epart + (size_t)i * 8;
    float s = p[0] + p[1] + p[2] + p[3] + p[4] + p[5] + p[6] + p[7];
    rs[i] = 1.0f / s;
}

// l2s[b][l][h*128+d] = tf32( l2 * rs[b,h,l] )
__global__ void scale_l2(const float4* __restrict__ l12v, const float* __restrict__ rs,
                         float4* __restrict__ l2s)
{
    int i = blockIdx.x * 256 + threadIdx.x;     // 1048576 -> 4096 blocks
    int hd4 = i & 255, l = (i >> 8) & 255, b = i >> 16;
    int h = hd4 >> 5;
    float r = rs[((size_t)b * 8 + h) * 256 + l];
    float4 v = l12v[(size_t)b * (LL_ * 2 * HD_ / 4) + (size_t)l * (2 * HD_ / 4) + HD_ / 4 + hd4];
    l2s[(size_t)b * (LL_ * HD_ / 4) + (size_t)l * (HD_ / 4) + hd4] =
        make_float4(tf32f(v.x * r), tf32f(v.y * r), tf32f(v.z * r), tf32f(v.w * r));
}

// ================= global kernels =================
__global__ __launch_bounds__(256, 2)
void gemm_proj(const float* __restrict__ ligr, const float* __restrict__ protr,
               const float* __restrict__ w, const float* __restrict__ bb,
               const float* __restrict__ bp1, const float* __restrict__ bp2,
               float* __restrict__ l12, float* __restrict__ p1, float* __restrict__ p2t)
{
    extern __shared__ float sm[];
    int id = blockIdx.x;
    if (id < 512) {
        int my = id >> 4, nx = id & 15;
        cp_body<1, true, true>(ligr, w + OW_L1, bb, l12,
                               128, 128, 128, 2048, my * 128, nx * 128, sm);
    } else if (id < 1536) {
        int id2 = id - 512;
        int my = id2 >> 3, nx = id2 & 7;
        cp_body<1, true, true>(protr, w + OW_P1, bp1, p1,
                               128, 128, 128, 1024, my * 128, nx * 128, sm);
    } else {
        int id2 = id - 1536;
        int zb = id2 >> 6, rem = id2 & 63;
        int my = rem >> 3, nx = rem & 7;
        cp_body<2, true, true>(w + OW_P2, protr + (size_t)zb * LP_ * HID_, bp2,
                               p2t + (size_t)zb * HD_ * LP_,
                               128, 128, 128, 1024, my * 128, nx * 128, sm);
    }
}

template<int BIASM, bool RELU, bool ROUND>
__global__ __launch_bounds__(256, 2)
void gemm_cp2(const float* __restrict__ A0, const float* __restrict__ B0,
              const float* __restrict__ b0, float* __restrict__ C0, int n0,
              const float* __restrict__ A1, const float* __restrict__ B1,
              const float* __restrict__ b1, float* __restrict__ C1,
              int K, int lda, int ldb, int ldc)
{
    extern __shared__ float sm[];
    int id = blockIdx.x;
    if (id < n0)
        cp_body<BIASM, RELU, ROUND>(A0, B0, b0, C0, K, lda, ldb, ldc, id * 128, 0, sm);
    else
        cp_body<BIASM, RELU, ROUND>(A1, B1, b1, C1, K, lda, ldb, ldc, (id - n0) * 128, 0, sm);
}

// fused attention-output, bf16 att (long lig3 CTAs first, then prot3)
__global__ __launch_bounds__(256, 2)
void gemm_av(const __nv_bfloat16* __restrict__ att, const float* __restrict__ p2t,
             const float* __restrict__ l2s, const float* __restrict__ rs,
             float* __restrict__ lig3, float* __restrict__ prot3)
{
    extern __shared__ float sm[];
    int id = blockIdx.x;
    if (id < 256) {
        int z = id & 127, my = id >> 7;
        int zb = z >> 3, zh = z & 7;
        const __nv_bfloat16* A = att + (size_t)zb * ((size_t)H_ * LL_ * LP_) + (size_t)zh * (LL_ * LP_);
        const float* Bp = p2t + (size_t)zb * (HD_ * LP_) + (size_t)zh * (128 * LP_);
        float* C = lig3 + (size_t)zb * (LL_ * HD_) + zh * 128;
        const float* rsz = rs + (size_t)z * 256;
        cp_bf_body<3, false, true>(A, Bp, rsz, C, 1024, LP_, LP_, HD_, my * 128, 0, sm);
    } else {
        int id2 = id - 256;
        int z = id2 >> 3, my = id2 & 7;
        int zb = z >> 3, zh = z & 7;
        const __nv_bfloat16* A = att + (size_t)zb * ((size_t)H_ * LL_ * LP_) + (size_t)zh * (LL_ * LP_);
        const float* Bl = l2s + (size_t)zb * (LL_ * HD_) + zh * 128;
        float* C = prot3 + (size_t)zb * (LP_ * HD_) + zh * 128;
        kk_bf_body<true>(A, Bl, C, 256, LP_, HD_, HD_, my * 128, 0, sm);
    }
}

// ---------------- merged preprocessing ----------------
// 131072 + 524288 + 2048 = 657408 threads -> 2568 blocks of 256
__global__ void preproc(const float4* __restrict__ lig, const float4* __restrict__ prot,
                        const float* __restrict__ bl1, const float* __restrict__ bl2,
                        float4* __restrict__ ligr, float4* __restrict__ protr,
                        float4* __restrict__ lcat, float4* __restrict__ pcat,
                        float* __restrict__ bb)
{
    int i = blockIdx.x * 256 + threadIdx.x;
    const int n1 = B_ * LL_ * HID_ / 4;   // 131072
    const int n2 = B_ * LP_ * HID_ / 4;   // 524288
    if (i < n1) {
        float4 v = lig[i];
        v = make_float4(tf32f(v.x), tf32f(v.y), tf32f(v.z), tf32f(v.w));
        ligr[i] = v;
        int r = i >> 5, c = i & 31;
        lcat[(size_t)r * 64 + 32 + c] = v;
    } else if (i < n1 + n2) {
        int j = i - n1;
        float4 v = prot[j];
        v = make_float4(tf32f(v.x), tf32f(v.y), tf32f(v.z), tf32f(v.w));
        protr[j] = v;
        int r = j >> 5, c = j & 31;
        pcat[(size_t)r * 64 + 32 + c] = v;
    } else {
        int j = i - n1 - n2;
        if (j < 1024) bb[j] = bl1[j];
        else if (j < 2048) bb[j] = bl2[j - 1024];
    }
}

__global__ void transpose_round8(const float* w0, const float* w1, const float* w2,
                                 const float* w3, const float* w4, const float* w5,
                                 const float* w6, const float* w7, float* wb)
{
    const float* ins[8] = {w0, w1, w2, w3, w4, w5, w6, w7};
    const int Rs[8]   = {128, 128, 128, 128, 1024, 1024, 256, 256};
    const int Cs[8]   = {1024, 1024, 1024, 1024, 128, 128, 128, 128};
    const int offs[8] = {OW_L1, OW_L2, OW_P1, OW_P2, OW_11, OW_21, OW_12, OW_22};
    int zi = blockIdx.z;
    int R = Rs[zi], C = Cs[zi];
    int bx = blockIdx.x * 32, by = blockIdx.y * 32;
    if (bx >= C || by >= R) return;
    const float* in = ins[zi];
    float* out = wb + offs[zi];

    __shared__ float t[32][33];
    int tx = threadIdx.x, ty = threadIdx.y;
#pragma unroll
    for (int j = 0; j < 32; j += 8)
        t[ty + j][tx] = in[(size_t)(by + ty + j) * C + bx + tx];
    __syncthreads();
#pragma unroll
    for (int j = 0; j < 32; j += 8)
        out[(size_t)(bx + ty + j) * R + by + tx] = tf32f(t[tx][ty + j]);
}

// ---------------- launcher ----------------
extern "C" void kernel_launch(void* const* d_in, const int* in_sizes, int n_in,
                              void* d_out, int out_size)
{
    const float* ligand = (const float*)d_in[0];
    const float* prot   = (const float*)d_in[1];
    const float* inter  = (const float*)d_in[2];
    const float* Wl1 = (const float*)d_in[3];  const float* bl1 = (const float*)d_in[4];
    const float* Wl2 = (const float*)d_in[5];  const float* bl2 = (const float*)d_in[6];
    const float* Wp1 = (const float*)d_in[7];  const float* bp1 = (const float*)d_in[8];
    const float* Wp2 = (const float*)d_in[9];  const float* bp2 = (const float*)d_in[10];
    const float* W11 = (const float*)d_in[11]; const float* b11 = (const float*)d_in[12];
    const float* W12 = (const float*)d_in[13]; const float* b12 = (const float*)d_in[14];
    const float* W21 = (const float*)d_in[15]; const float* b21 = (const float*)d_in[16];
    const float* W22 = (const float*)d_in[17]; const float* b22 = (const float*)d_in[18];

    float* out_lig  = (float*)d_out;
    float* out_prot = out_lig + (size_t)B_ * LL_ * HID_;

    float *l12, *p1, *p2t, *lig3, *prot3, *lcat, *pcat, *ligr, *protr, *w, *bb;
    float *l2s, *epart, *rs;
    __nv_bfloat16* att;
    cudaGetSymbolAddress((void**)&l12, g_l12);
    cudaGetSymbolAddress((void**)&p1, g_p1);
    cudaGetSymbolAddress((void**)&p2t, g_p2t);
    cudaGetSymbolAddress((void**)&att, g_att);
    cudaGetSymbolAddress((void**)&lig3, g_lig3);
    cudaGetSymbolAddress((void**)&prot3, g_prot3);
    cudaGetSymbolAddress((void**)&lcat, g_ligcat);
    cudaGetSymbolAddress((void**)&pcat, g_protcat);
    cudaGetSymbolAddress((void**)&ligr, g_ligr);
    cudaGetSymbolAddress((void**)&protr, g_protr);
    cudaGetSymbolAddress((void**)&w, g_w);
    cudaGetSymbolAddress((void**)&bb, g_b12);
    cudaGetSymbolAddress((void**)&l2s, g_l2s);
    cudaGetSymbolAddress((void**)&epart, g_epart);
    cudaGetSymbolAddress((void**)&rs, g_rs);

    dim3 blk(256);
    const int SMEM = 49152;

    // --- preprocessing ---
    preproc<<<2568, 256>>>((const float4*)ligand, (const float4*)prot, bl1, bl2,
                           (float4*)ligr, (float4*)protr,
                           (float4*)lcat, (float4*)pcat, bb);
    transpose_round8<<<dim3(32, 32, 8), dim3(32, 8)>>>(
        Wl1, Wl2, Wp1, Wp2, W11, W21, W12, W22, w);

    // --- all three projections in one 2560-CTA launch ---
    gemm_proj<<<2560, blk, SMEM>>>(ligr, protr, w, bb, bp1, bp2, l12, p1, p2t);

    // --- energy with fused exp/gating epilogue (bf16 att) + partial row sums ---
    gemm_energy<<<dim3(8, 2, 128), blk, SMEM>>>(l12, p1, inter, att, epart);

    // --- reciprocal row sums + scaled l2 ---
    reduce_rs<<<128, 256>>>(epart, rs);
    scale_l2<<<4096, 256>>>((const float4*)l12, rs, (float4*)l2s);

    // --- fused lig3 + prot3 (1280 CTAs, long CTAs first, bf16 att reads) ---
    gemm_av<<<1280, blk, SMEM>>>(att, p2t, l2s, rs, lig3, prot3);

    // --- paired branch MLP stage 1 ---
    gemm_cp2<1,false,true><<<160, blk, SMEM>>>(
        lig3,  w + OW_11, b11, lcat, 32,
        prot3, w + OW_21, b21, pcat,
        1024, 1024, 1024, 256);

    // --- paired branch MLP stage 2 ---
    gemm_cp2<1,true,false><<<160, blk, SMEM>>>(
        lcat, w + OW_12, b12, out_lig, 32,
        pcat, w + OW_22, b22, out_prot,
        256, 256, 256, 128);
}